// round 13
// baseline (speedup 1.0000x reference)
#include <cuda_runtime.h>
#include <cuda_fp16.h>
#include <stdint.h>

// Int8SymmetricLinear via single-pass fp16 mma.sync on sm_103.
// out[M,N] = wscale[n] * (X[M,K] @ W[N,K]^T) + bias[n]
// W int32 in [-127,127] -> exact in fp16; X rounded to fp16 (rel err ~2e-4).
//
// Round 13: round-9 structure (best: 1548.8us — 3-stage cp.async, two syncs
// per chunk, grouped L2 swizzle) + EXPLICIT FRAGMENT DOUBLE-BUFFERING in the
// inner loop: ldmatrix for k16+1 issues into the alternate register buffer
// while the 32 MMAs of k16 drain, hiding LDSM latency at k16 boundaries.

#define MDIM 8192
#define NDIM 11008
#define KDIM 4096

#define TILES_M 64
#define TILES_N 86
#define GROUP_M 8
#define GROUP_SZ (GROUP_M * TILES_N)   // 688

__device__ __align__(16) __half g_Xh[(size_t)MDIM * KDIM];
__device__ __align__(16) __half g_Wh[(size_t)NDIM * KDIM];

// ---------------- prep kernels ----------------

__global__ void __launch_bounds__(256)
prep_x_kernel(const float* __restrict__ X)
{
    size_t i4 = (size_t)blockIdx.x * 256 + threadIdx.x;
    float4 v = reinterpret_cast<const float4*>(X)[i4];
    uint2 o;
    __half2 p0 = __floats2half2_rn(v.x, v.y);
    __half2 p1 = __floats2half2_rn(v.z, v.w);
    o.x = *reinterpret_cast<uint32_t*>(&p0);
    o.y = *reinterpret_cast<uint32_t*>(&p1);
    reinterpret_cast<uint2*>(g_Xh)[i4] = o;
}

__global__ void __launch_bounds__(256)
prep_w_kernel(const int* __restrict__ W)
{
    size_t i4 = (size_t)blockIdx.x * 256 + threadIdx.x;
    int4 v = reinterpret_cast<const int4*>(W)[i4];
    uint2 o;
    __half2 p0 = __floats2half2_rn(__int2float_rn(v.x), __int2float_rn(v.y));
    __half2 p1 = __floats2half2_rn(__int2float_rn(v.z), __int2float_rn(v.w));
    o.x = *reinterpret_cast<uint32_t*>(&p0);
    o.y = *reinterpret_cast<uint32_t*>(&p1);
    reinterpret_cast<uint2*>(g_Wh)[i4] = o;
}

// ---------------- GEMM ----------------

#define BM 128
#define BN 128
#define BK 64                       // fp16 elems per chunk -> 128B rows
#define TILE_B (128 * 128)          // 16KB
#define OFF_A 0
#define OFF_B TILE_B
#define STAGE_B (2 * TILE_B)        // 32KB
#define NSTAGE 3
#define SMEM_SZ (NSTAGE * STAGE_B)  // 96KB

static __device__ __forceinline__ uint32_t smem_u32(const void* p) {
    uint32_t a;
    asm("{ .reg .u64 t; cvta.to.shared.u64 t, %1; cvt.u32.u64 %0, t; }" : "=r"(a) : "l"(p));
    return a;
}
static __device__ __forceinline__ void cp16(uint32_t saddr, const void* g) {
    asm volatile("cp.async.cg.shared.global [%0], [%1], 16;" :: "r"(saddr), "l"(g));
}
static __device__ __forceinline__ void cp_commit() {
    asm volatile("cp.async.commit_group;" ::: "memory");
}
template <int N_>
static __device__ __forceinline__ void cp_wait() {
    asm volatile("cp.async.wait_group %0;" :: "n"(N_) : "memory");
}
static __device__ __forceinline__ void ldm4(uint32_t addr, uint32_t* r) {
    asm volatile("ldmatrix.sync.aligned.m8n8.x4.shared.b16 {%0,%1,%2,%3}, [%4];"
                 : "=r"(r[0]), "=r"(r[1]), "=r"(r[2]), "=r"(r[3]) : "r"(addr));
}
static __device__ __forceinline__ void mma16816(float* c, const uint32_t* a, const uint32_t* b) {
    asm volatile(
        "mma.sync.aligned.m16n8k16.row.col.f32.f16.f16.f32 "
        "{%0,%1,%2,%3}, {%4,%5,%6,%7}, {%8,%9}, {%0,%1,%2,%3};"
        : "+f"(c[0]), "+f"(c[1]), "+f"(c[2]), "+f"(c[3])
        : "r"(a[0]), "r"(a[1]), "r"(a[2]), "r"(a[3]), "r"(b[0]), "r"(b[1]));
}
// row-stride 128B, 16B slots, XOR-8 swizzle
static __device__ __forceinline__ uint32_t sw_addr(uint32_t base, int row, int slot) {
    return base + row * 128 + ((slot ^ (row & 7)) << 4);
}

extern __shared__ char smem_raw[];

__global__ void __launch_bounds__(128, 2)
gemm_f16_kernel(const float* __restrict__ Wscale,
                const float* __restrict__ Bias,
                float* __restrict__ Out)
{
    const int tid    = threadIdx.x;
    const int lane   = tid & 31;
    const int wid    = tid >> 5;      // 0..3
    const int warp_m = wid >> 1;      // 0..1 -> m offset 64*warp_m
    const int warp_n = wid & 1;       // 0..1 -> n offset 64*warp_n

    // ---- grouped tile swizzle (GROUP_M M-tiles per N step) ----
    const int bid      = blockIdx.x;
    const int group_id = bid / GROUP_SZ;
    const int in_group = bid - group_id * GROUP_SZ;
    const int pid_m    = group_id * GROUP_M + (in_group % GROUP_M);
    const int pid_n    = in_group / GROUP_M;
    const int bm = pid_m * BM;
    const int bn = pid_n * BN;

    const uint32_t sb = smem_u32(smem_raw);

    // loader mapping: 1024 16B-slots per tile, 8 per thread per tile
    const int ld_row0 = tid >> 3;         // 0..15, +16 per step
    const int ld_slot = tid & 7;

    // ldmatrix row/slot bases (per thread, loop-invariant)
    const int b_row = warp_n * 64 + ((lane & 16) >> 1) + (lane & 7);
    const int b_sl  = (lane >> 3) & 1;
    const int a_row = warp_m * 64 + (lane & 15);
    const int a_sl  = lane >> 4;

    float acc[4][8][4];
#pragma unroll
    for (int i = 0; i < 4; i++)
#pragma unroll
        for (int j = 0; j < 8; j++)
#pragma unroll
            for (int q = 0; q < 4; q++) acc[i][j][q] = 0.0f;

    const int NCH = KDIM / BK;   // 64

    auto load_chunk = [&](int c, int stg) {
        const uint32_t st = sb + stg * STAGE_B;
        const size_t kt = (size_t)c * BK;
#pragma unroll
        for (int u = 0; u < 8; u++) {
            const int row = ld_row0 + u * 16;
            const uint32_t so = (uint32_t)(row * 128 + ((ld_slot ^ (row & 7)) << 4));
            const size_t gx = (size_t)(bm + row) * KDIM + kt + ld_slot * 8;
            const size_t gw = (size_t)(bn + row) * KDIM + kt + ld_slot * 8;
            cp16(st + OFF_A + so, g_Xh + gx);
            cp16(st + OFF_B + so, g_Wh + gw);
        }
    };

    load_chunk(0, 0); cp_commit();
    load_chunk(1, 1); cp_commit();
    load_chunk(2, 2); cp_commit();

    for (int c = 0; c < NCH; c++) {
        const int stg = c % NSTAGE;
        cp_wait<2>();
        __syncthreads();

        const uint32_t atl = sb + stg * STAGE_B + OFF_A;
        const uint32_t btl = sb + stg * STAGE_B + OFF_B;

        // ---- fragment double-buffered inner loop ----
        uint32_t af[2][4][4], bf[2][4][4];

        // prologue: load k16=0 fragments into buffer 0
#pragma unroll
        for (int nb = 0; nb < 4; nb++)
            ldm4(sw_addr(btl, b_row + nb * 16, b_sl), bf[0][nb]);
#pragma unroll
        for (int mb = 0; mb < 4; mb++)
            ldm4(sw_addr(atl, a_row + mb * 16, a_sl), af[0][mb]);

#pragma unroll
        for (int k16 = 0; k16 < 4; k16++) {
            const int cur = k16 & 1;
            const int nxt = cur ^ 1;
            if (k16 < 3) {
                const int slot_b = 2 * (k16 + 1) + b_sl;
                const int slot_a = 2 * (k16 + 1) + a_sl;
#pragma unroll
                for (int nb = 0; nb < 4; nb++)
                    ldm4(sw_addr(btl, b_row + nb * 16, slot_b), bf[nxt][nb]);
#pragma unroll
                for (int mb = 0; mb < 4; mb++)
                    ldm4(sw_addr(atl, a_row + mb * 16, slot_a), af[nxt][mb]);
            }
#pragma unroll
            for (int mb = 0; mb < 4; mb++)
#pragma unroll
                for (int nb = 0; nb < 4; nb++) {
                    mma16816(acc[mb][nb * 2 + 0], af[cur][mb], &bf[cur][nb][0]);
                    mma16816(acc[mb][nb * 2 + 1], af[cur][mb], &bf[cur][nb][2]);
                }
        }

        __syncthreads();
        if (c + NSTAGE < NCH) load_chunk(c + NSTAGE, stg);
        cp_commit();
    }

    // ---- epilogue: scale + bias, float2 stores ----
    const int n_base = bn + warp_n * 64 + (lane & 3) * 2;
    float2 sc[8], bi[8];
#pragma unroll
    for (int nj = 0; nj < 8; nj++) {
        sc[nj] = *reinterpret_cast<const float2*>(Wscale + n_base + nj * 8);
        bi[nj] = *reinterpret_cast<const float2*>(Bias   + n_base + nj * 8);
    }
#pragma unroll
    for (int mb = 0; mb < 4; mb++) {
        const int m0 = bm + warp_m * 64 + mb * 16 + (lane >> 2);
#pragma unroll
        for (int nj = 0; nj < 8; nj++) {
            const int n = n_base + nj * 8;
            float2 o0, o1;
            o0.x = fmaf(acc[mb][nj][0], sc[nj].x, bi[nj].x);
            o0.y = fmaf(acc[mb][nj][1], sc[nj].y, bi[nj].y);
            o1.x = fmaf(acc[mb][nj][2], sc[nj].x, bi[nj].x);
            o1.y = fmaf(acc[mb][nj][3], sc[nj].y, bi[nj].y);
            *reinterpret_cast<float2*>(Out + (size_t)m0 * NDIM + n)       = o0;
            *reinterpret_cast<float2*>(Out + (size_t)(m0 + 8) * NDIM + n) = o1;
        }
    }
}

// ---------------- launch ----------------

extern "C" void kernel_launch(void* const* d_in, const int* in_sizes, int n_in,
                              void* d_out, int out_size)
{
    const float* X      = (const float*)d_in[0];   // [M, K] fp32
    const int*   W      = (const int*)d_in[1];     // [N, K] int32 (int8 values)
    const float* Wscale = (const float*)d_in[2];   // [N] fp32
    const float* Bias   = (const float*)d_in[3];   // [N] fp32
    float*       Out    = (float*)d_out;           // [M, N] fp32

    prep_x_kernel<<<(size_t)MDIM * KDIM / (256 * 4), 256>>>(X);
    prep_w_kernel<<<(size_t)NDIM * KDIM / (256 * 4), 256>>>(W);

    static int smem_set = 0;
    if (!smem_set) {
        cudaFuncSetAttribute(gemm_f16_kernel,
                             cudaFuncAttributeMaxDynamicSharedMemorySize, SMEM_SZ);
        smem_set = 1;
    }
    gemm_f16_kernel<<<TILES_M * TILES_N, 128, SMEM_SZ>>>(Wscale, Bias, Out);
}

// round 14
// speedup vs baseline: 1.0757x; 1.0757x over previous
#include <cuda_runtime.h>
#include <cuda_fp16.h>
#include <stdint.h>

// Int8SymmetricLinear via single-pass fp16 mma.sync on sm_103.
// out[M,N] = wscale[n] * (X[M,K] @ W[N,K]^T) + bias[n]
// W int32 in [-127,127] -> exact in fp16; X rounded to fp16 (rel err ~2e-4).
//
// Round 14: round-9 GEMM verbatim (best: 1548.8us) + two out-of-mainloop fixes:
//  1. GROUP_M 8 -> 16: balances per-wave DRAM footprint (A 16.8MB + B 19.4MB
//     = 36MB/wave vs 47MB), ~200MB less total DRAM traffic.
//  2. Fused single prep kernel (one launch instead of two serial ones).

#define MDIM 8192
#define NDIM 11008
#define KDIM 4096

#define TILES_M 64
#define TILES_N 86
#define GROUP_M 16
#define GROUP_SZ (GROUP_M * TILES_N)   // 1376

__device__ __align__(16) __half g_Xh[(size_t)MDIM * KDIM];
__device__ __align__(16) __half g_Wh[(size_t)NDIM * KDIM];

// ---------------- fused prep kernel ----------------
// one thread = one 4-element unit; X units first, then W units.

#define NXU ((size_t)MDIM * KDIM / 4)      // 8.39M
#define NWU ((size_t)NDIM * KDIM / 4)      // 11.27M

__global__ void __launch_bounds__(256)
prep_kernel(const float* __restrict__ X, const int* __restrict__ W)
{
    const size_t u = (size_t)blockIdx.x * 256 + threadIdx.x;
    if (u < NXU) {
        float4 v = reinterpret_cast<const float4*>(X)[u];
        uint2 o;
        __half2 p0 = __floats2half2_rn(v.x, v.y);
        __half2 p1 = __floats2half2_rn(v.z, v.w);
        o.x = *reinterpret_cast<uint32_t*>(&p0);
        o.y = *reinterpret_cast<uint32_t*>(&p1);
        reinterpret_cast<uint2*>(g_Xh)[u] = o;
    } else {
        const size_t w = u - NXU;
        if (w < NWU) {
            int4 v = reinterpret_cast<const int4*>(W)[w];
            uint2 o;
            __half2 p0 = __floats2half2_rn(__int2float_rn(v.x), __int2float_rn(v.y));
            __half2 p1 = __floats2half2_rn(__int2float_rn(v.z), __int2float_rn(v.w));
            o.x = *reinterpret_cast<uint32_t*>(&p0);
            o.y = *reinterpret_cast<uint32_t*>(&p1);
            reinterpret_cast<uint2*>(g_Wh)[w] = o;
        }
    }
}

// ---------------- GEMM ----------------

#define BM 128
#define BN 128
#define BK 64                       // fp16 elems per chunk -> 128B rows
#define TILE_B (128 * 128)          // 16KB
#define OFF_A 0
#define OFF_B TILE_B
#define STAGE_B (2 * TILE_B)        // 32KB
#define NSTAGE 3
#define SMEM_SZ (NSTAGE * STAGE_B)  // 96KB

static __device__ __forceinline__ uint32_t smem_u32(const void* p) {
    uint32_t a;
    asm("{ .reg .u64 t; cvta.to.shared.u64 t, %1; cvt.u32.u64 %0, t; }" : "=r"(a) : "l"(p));
    return a;
}
static __device__ __forceinline__ void cp16(uint32_t saddr, const void* g) {
    asm volatile("cp.async.cg.shared.global [%0], [%1], 16;" :: "r"(saddr), "l"(g));
}
static __device__ __forceinline__ void cp_commit() {
    asm volatile("cp.async.commit_group;" ::: "memory");
}
template <int N_>
static __device__ __forceinline__ void cp_wait() {
    asm volatile("cp.async.wait_group %0;" :: "n"(N_) : "memory");
}
static __device__ __forceinline__ void ldm4(uint32_t addr, uint32_t* r) {
    asm volatile("ldmatrix.sync.aligned.m8n8.x4.shared.b16 {%0,%1,%2,%3}, [%4];"
                 : "=r"(r[0]), "=r"(r[1]), "=r"(r[2]), "=r"(r[3]) : "r"(addr));
}
static __device__ __forceinline__ void mma16816(float* c, const uint32_t* a, const uint32_t* b) {
    asm volatile(
        "mma.sync.aligned.m16n8k16.row.col.f32.f16.f16.f32 "
        "{%0,%1,%2,%3}, {%4,%5,%6,%7}, {%8,%9}, {%0,%1,%2,%3};"
        : "+f"(c[0]), "+f"(c[1]), "+f"(c[2]), "+f"(c[3])
        : "r"(a[0]), "r"(a[1]), "r"(a[2]), "r"(a[3]), "r"(b[0]), "r"(b[1]));
}
// row-stride 128B, 16B slots, XOR-8 swizzle
static __device__ __forceinline__ uint32_t sw_addr(uint32_t base, int row, int slot) {
    return base + row * 128 + ((slot ^ (row & 7)) << 4);
}

extern __shared__ char smem_raw[];

__global__ void __launch_bounds__(128, 2)
gemm_f16_kernel(const float* __restrict__ Wscale,
                const float* __restrict__ Bias,
                float* __restrict__ Out)
{
    const int tid    = threadIdx.x;
    const int lane   = tid & 31;
    const int wid    = tid >> 5;      // 0..3
    const int warp_m = wid >> 1;      // 0..1 -> m offset 64*warp_m
    const int warp_n = wid & 1;       // 0..1 -> n offset 64*warp_n

    // ---- grouped tile swizzle (GROUP_M M-tiles per N step) ----
    const int bid      = blockIdx.x;
    const int group_id = bid / GROUP_SZ;
    const int in_group = bid - group_id * GROUP_SZ;
    const int pid_m    = group_id * GROUP_M + (in_group % GROUP_M);
    const int pid_n    = in_group / GROUP_M;
    const int bm = pid_m * BM;
    const int bn = pid_n * BN;

    const uint32_t sb = smem_u32(smem_raw);

    // loader mapping: 1024 16B-slots per tile, 8 per thread per tile
    const int ld_row0 = tid >> 3;         // 0..15, +16 per step
    const int ld_slot = tid & 7;

    float acc[4][8][4];
#pragma unroll
    for (int i = 0; i < 4; i++)
#pragma unroll
        for (int j = 0; j < 8; j++)
#pragma unroll
            for (int q = 0; q < 4; q++) acc[i][j][q] = 0.0f;

    const int NCH = KDIM / BK;   // 64

    auto load_chunk = [&](int c, int stg) {
        const uint32_t st = sb + stg * STAGE_B;
        const size_t kt = (size_t)c * BK;
#pragma unroll
        for (int u = 0; u < 8; u++) {
            const int row = ld_row0 + u * 16;
            const uint32_t so = (uint32_t)(row * 128 + ((ld_slot ^ (row & 7)) << 4));
            const size_t gx = (size_t)(bm + row) * KDIM + kt + ld_slot * 8;
            const size_t gw = (size_t)(bn + row) * KDIM + kt + ld_slot * 8;
            cp16(st + OFF_A + so, g_Xh + gx);
            cp16(st + OFF_B + so, g_Wh + gw);
        }
    };

    load_chunk(0, 0); cp_commit();
    load_chunk(1, 1); cp_commit();
    load_chunk(2, 2); cp_commit();

    for (int c = 0; c < NCH; c++) {
        const int stg = c % NSTAGE;
        cp_wait<2>();
        __syncthreads();

        const uint32_t atl = sb + stg * STAGE_B + OFF_A;
        const uint32_t btl = sb + stg * STAGE_B + OFF_B;

#pragma unroll
        for (int k16 = 0; k16 < 4; k16++) {
            uint32_t bf[4][4];     // 4 n16-blocks -> 8 n8 frags
#pragma unroll
            for (int nb = 0; nb < 4; nb++) {
                const int row  = warp_n * 64 + nb * 16 + ((lane & 16) >> 1) + (lane & 7);
                const int slot = 2 * k16 + ((lane >> 3) & 1);
                ldm4(sw_addr(btl, row, slot), bf[nb]);
            }
            uint32_t af[4][4];     // 4 m16-blocks
#pragma unroll
            for (int mb = 0; mb < 4; mb++) {
                const int row  = warp_m * 64 + mb * 16 + (lane & 15);
                const int slot = 2 * k16 + (lane >> 4);
                ldm4(sw_addr(atl, row, slot), af[mb]);
            }
#pragma unroll
            for (int mb = 0; mb < 4; mb++)
#pragma unroll
                for (int nb = 0; nb < 4; nb++) {
                    mma16816(acc[mb][nb * 2 + 0], af[mb], &bf[nb][0]);
                    mma16816(acc[mb][nb * 2 + 1], af[mb], &bf[nb][2]);
                }
        }

        __syncthreads();
        if (c + NSTAGE < NCH) load_chunk(c + NSTAGE, stg);
        cp_commit();
    }

    // ---- epilogue: scale + bias, float2 stores ----
    const int n_base = bn + warp_n * 64 + (lane & 3) * 2;
    float2 sc[8], bi[8];
#pragma unroll
    for (int nj = 0; nj < 8; nj++) {
        sc[nj] = *reinterpret_cast<const float2*>(Wscale + n_base + nj * 8);
        bi[nj] = *reinterpret_cast<const float2*>(Bias   + n_base + nj * 8);
    }
#pragma unroll
    for (int mb = 0; mb < 4; mb++) {
        const int m0 = bm + warp_m * 64 + mb * 16 + (lane >> 2);
#pragma unroll
        for (int nj = 0; nj < 8; nj++) {
            const int n = n_base + nj * 8;
            float2 o0, o1;
            o0.x = fmaf(acc[mb][nj][0], sc[nj].x, bi[nj].x);
            o0.y = fmaf(acc[mb][nj][1], sc[nj].y, bi[nj].y);
            o1.x = fmaf(acc[mb][nj][2], sc[nj].x, bi[nj].x);
            o1.y = fmaf(acc[mb][nj][3], sc[nj].y, bi[nj].y);
            *reinterpret_cast<float2*>(Out + (size_t)m0 * NDIM + n)       = o0;
            *reinterpret_cast<float2*>(Out + (size_t)(m0 + 8) * NDIM + n) = o1;
        }
    }
}

// ---------------- launch ----------------

extern "C" void kernel_launch(void* const* d_in, const int* in_sizes, int n_in,
                              void* d_out, int out_size)
{
    const float* X      = (const float*)d_in[0];   // [M, K] fp32
    const int*   W      = (const int*)d_in[1];     // [N, K] int32 (int8 values)
    const float* Wscale = (const float*)d_in[2];   // [N] fp32
    const float* Bias   = (const float*)d_in[3];   // [N] fp32
    float*       Out    = (float*)d_out;           // [M, N] fp32

    const size_t total_units = NXU + NWU;
    const int prep_blocks = (int)((total_units + 255) / 256);
    prep_kernel<<<prep_blocks, 256>>>(X, W);

    static int smem_set = 0;
    if (!smem_set) {
        cudaFuncSetAttribute(gemm_f16_kernel,
                             cudaFuncAttributeMaxDynamicSharedMemorySize, SMEM_SZ);
        smem_set = 1;
    }
    gemm_f16_kernel<<<TILES_M * TILES_N, 128, SMEM_SZ>>>(Wscale, Bias, Out);
}

// round 15
// speedup vs baseline: 1.0825x; 1.0063x over previous
#include <cuda_runtime.h>
#include <cuda_fp16.h>
#include <stdint.h>

// Int8SymmetricLinear via single-pass fp16 mma.sync on sm_103.
// out[M,N] = wscale[n] * (X[M,K] @ W[N,K]^T) + bias[n]
// W int32 in [-127,127] -> exact in fp16; X rounded to fp16 (rel err ~2e-4).
//
// Round 15: GEMM frozen (82.4% tensor pipe, converged per rounds 10-14).
// Prep optimized: 8 elems/thread, 16B vectorized stores (was 8B), halving
// prep instruction count; prep is issue-limited (13%) not BW-limited (70%).

#define MDIM 8192
#define NDIM 11008
#define KDIM 4096

#define TILES_M 64
#define TILES_N 86
#define GROUP_M 16
#define GROUP_SZ (GROUP_M * TILES_N)   // 1376

__device__ __align__(16) __half g_Xh[(size_t)MDIM * KDIM];
__device__ __align__(16) __half g_Wh[(size_t)NDIM * KDIM];

// ---------------- fused prep kernel ----------------
// one thread = one 8-element unit (two 16B reads -> one 16B write).

#define NXU8 ((size_t)MDIM * KDIM / 8)      // 4.19M
#define NWU8 ((size_t)NDIM * KDIM / 8)      // 5.64M

__global__ void __launch_bounds__(512)
prep_kernel(const float* __restrict__ X, const int* __restrict__ W)
{
    const size_t u = (size_t)blockIdx.x * 512 + threadIdx.x;
    if (u < NXU8) {
        const float4* src = reinterpret_cast<const float4*>(X) + u * 2;
        float4 v0 = src[0];
        float4 v1 = src[1];
        uint4 o;
        __half2 p0 = __floats2half2_rn(v0.x, v0.y);
        __half2 p1 = __floats2half2_rn(v0.z, v0.w);
        __half2 p2 = __floats2half2_rn(v1.x, v1.y);
        __half2 p3 = __floats2half2_rn(v1.z, v1.w);
        o.x = *reinterpret_cast<uint32_t*>(&p0);
        o.y = *reinterpret_cast<uint32_t*>(&p1);
        o.z = *reinterpret_cast<uint32_t*>(&p2);
        o.w = *reinterpret_cast<uint32_t*>(&p3);
        reinterpret_cast<uint4*>(g_Xh)[u] = o;
    } else {
        const size_t w = u - NXU8;
        if (w < NWU8) {
            const int4* src = reinterpret_cast<const int4*>(W) + w * 2;
            int4 v0 = src[0];
            int4 v1 = src[1];
            uint4 o;
            __half2 p0 = __floats2half2_rn(__int2float_rn(v0.x), __int2float_rn(v0.y));
            __half2 p1 = __floats2half2_rn(__int2float_rn(v0.z), __int2float_rn(v0.w));
            __half2 p2 = __floats2half2_rn(__int2float_rn(v1.x), __int2float_rn(v1.y));
            __half2 p3 = __floats2half2_rn(__int2float_rn(v1.z), __int2float_rn(v1.w));
            o.x = *reinterpret_cast<uint32_t*>(&p0);
            o.y = *reinterpret_cast<uint32_t*>(&p1);
            o.z = *reinterpret_cast<uint32_t*>(&p2);
            o.w = *reinterpret_cast<uint32_t*>(&p3);
            reinterpret_cast<uint4*>(g_Wh)[w] = o;
        }
    }
}

// ---------------- GEMM (frozen) ----------------

#define BM 128
#define BN 128
#define BK 64                       // fp16 elems per chunk -> 128B rows
#define TILE_B (128 * 128)          // 16KB
#define OFF_A 0
#define OFF_B TILE_B
#define STAGE_B (2 * TILE_B)        // 32KB
#define NSTAGE 3
#define SMEM_SZ (NSTAGE * STAGE_B)  // 96KB

static __device__ __forceinline__ uint32_t smem_u32(const void* p) {
    uint32_t a;
    asm("{ .reg .u64 t; cvta.to.shared.u64 t, %1; cvt.u32.u64 %0, t; }" : "=r"(a) : "l"(p));
    return a;
}
static __device__ __forceinline__ void cp16(uint32_t saddr, const void* g) {
    asm volatile("cp.async.cg.shared.global [%0], [%1], 16;" :: "r"(saddr), "l"(g));
}
static __device__ __forceinline__ void cp_commit() {
    asm volatile("cp.async.commit_group;" ::: "memory");
}
template <int N_>
static __device__ __forceinline__ void cp_wait() {
    asm volatile("cp.async.wait_group %0;" :: "n"(N_) : "memory");
}
static __device__ __forceinline__ void ldm4(uint32_t addr, uint32_t* r) {
    asm volatile("ldmatrix.sync.aligned.m8n8.x4.shared.b16 {%0,%1,%2,%3}, [%4];"
                 : "=r"(r[0]), "=r"(r[1]), "=r"(r[2]), "=r"(r[3]) : "r"(addr));
}
static __device__ __forceinline__ void mma16816(float* c, const uint32_t* a, const uint32_t* b) {
    asm volatile(
        "mma.sync.aligned.m16n8k16.row.col.f32.f16.f16.f32 "
        "{%0,%1,%2,%3}, {%4,%5,%6,%7}, {%8,%9}, {%0,%1,%2,%3};"
        : "+f"(c[0]), "+f"(c[1]), "+f"(c[2]), "+f"(c[3])
        : "r"(a[0]), "r"(a[1]), "r"(a[2]), "r"(a[3]), "r"(b[0]), "r"(b[1]));
}
// row-stride 128B, 16B slots, XOR-8 swizzle
static __device__ __forceinline__ uint32_t sw_addr(uint32_t base, int row, int slot) {
    return base + row * 128 + ((slot ^ (row & 7)) << 4);
}

extern __shared__ char smem_raw[];

__global__ void __launch_bounds__(128, 2)
gemm_f16_kernel(const float* __restrict__ Wscale,
                const float* __restrict__ Bias,
                float* __restrict__ Out)
{
    const int tid    = threadIdx.x;
    const int lane   = tid & 31;
    const int wid    = tid >> 5;      // 0..3
    const int warp_m = wid >> 1;      // 0..1 -> m offset 64*warp_m
    const int warp_n = wid & 1;       // 0..1 -> n offset 64*warp_n

    // ---- grouped tile swizzle (GROUP_M M-tiles per N step) ----
    const int bid      = blockIdx.x;
    const int group_id = bid / GROUP_SZ;
    const int in_group = bid - group_id * GROUP_SZ;
    const int pid_m    = group_id * GROUP_M + (in_group % GROUP_M);
    const int pid_n    = in_group / GROUP_M;
    const int bm = pid_m * BM;
    const int bn = pid_n * BN;

    const uint32_t sb = smem_u32(smem_raw);

    // loader mapping: 1024 16B-slots per tile, 8 per thread per tile
    const int ld_row0 = tid >> 3;         // 0..15, +16 per step
    const int ld_slot = tid & 7;

    float acc[4][8][4];
#pragma unroll
    for (int i = 0; i < 4; i++)
#pragma unroll
        for (int j = 0; j < 8; j++)
#pragma unroll
            for (int q = 0; q < 4; q++) acc[i][j][q] = 0.0f;

    const int NCH = KDIM / BK;   // 64

    auto load_chunk = [&](int c, int stg) {
        const uint32_t st = sb + stg * STAGE_B;
        const size_t kt = (size_t)c * BK;
#pragma unroll
        for (int u = 0; u < 8; u++) {
            const int row = ld_row0 + u * 16;
            const uint32_t so = (uint32_t)(row * 128 + ((ld_slot ^ (row & 7)) << 4));
            const size_t gx = (size_t)(bm + row) * KDIM + kt + ld_slot * 8;
            const size_t gw = (size_t)(bn + row) * KDIM + kt + ld_slot * 8;
            cp16(st + OFF_A + so, g_Xh + gx);
            cp16(st + OFF_B + so, g_Wh + gw);
        }
    };

    load_chunk(0, 0); cp_commit();
    load_chunk(1, 1); cp_commit();
    load_chunk(2, 2); cp_commit();

    for (int c = 0; c < NCH; c++) {
        const int stg = c % NSTAGE;
        cp_wait<2>();
        __syncthreads();

        const uint32_t atl = sb + stg * STAGE_B + OFF_A;
        const uint32_t btl = sb + stg * STAGE_B + OFF_B;

#pragma unroll
        for (int k16 = 0; k16 < 4; k16++) {
            uint32_t bf[4][4];     // 4 n16-blocks -> 8 n8 frags
#pragma unroll
            for (int nb = 0; nb < 4; nb++) {
                const int row  = warp_n * 64 + nb * 16 + ((lane & 16) >> 1) + (lane & 7);
                const int slot = 2 * k16 + ((lane >> 3) & 1);
                ldm4(sw_addr(btl, row, slot), bf[nb]);
            }
            uint32_t af[4][4];     // 4 m16-blocks
#pragma unroll
            for (int mb = 0; mb < 4; mb++) {
                const int row  = warp_m * 64 + mb * 16 + (lane & 15);
                const int slot = 2 * k16 + (lane >> 4);
                ldm4(sw_addr(atl, row, slot), af[mb]);
            }
#pragma unroll
            for (int mb = 0; mb < 4; mb++)
#pragma unroll
                for (int nb = 0; nb < 4; nb++) {
                    mma16816(acc[mb][nb * 2 + 0], af[mb], &bf[nb][0]);
                    mma16816(acc[mb][nb * 2 + 1], af[mb], &bf[nb][2]);
                }
        }

        __syncthreads();
        if (c + NSTAGE < NCH) load_chunk(c + NSTAGE, stg);
        cp_commit();
    }

    // ---- epilogue: scale + bias, float2 stores ----
    const int n_base = bn + warp_n * 64 + (lane & 3) * 2;
    float2 sc[8], bi[8];
#pragma unroll
    for (int nj = 0; nj < 8; nj++) {
        sc[nj] = *reinterpret_cast<const float2*>(Wscale + n_base + nj * 8);
        bi[nj] = *reinterpret_cast<const float2*>(Bias   + n_base + nj * 8);
    }
#pragma unroll
    for (int mb = 0; mb < 4; mb++) {
        const int m0 = bm + warp_m * 64 + mb * 16 + (lane >> 2);
#pragma unroll
        for (int nj = 0; nj < 8; nj++) {
            const int n = n_base + nj * 8;
            float2 o0, o1;
            o0.x = fmaf(acc[mb][nj][0], sc[nj].x, bi[nj].x);
            o0.y = fmaf(acc[mb][nj][1], sc[nj].y, bi[nj].y);
            o1.x = fmaf(acc[mb][nj][2], sc[nj].x, bi[nj].x);
            o1.y = fmaf(acc[mb][nj][3], sc[nj].y, bi[nj].y);
            *reinterpret_cast<float2*>(Out + (size_t)m0 * NDIM + n)       = o0;
            *reinterpret_cast<float2*>(Out + (size_t)(m0 + 8) * NDIM + n) = o1;
        }
    }
}

// ---------------- launch ----------------

extern "C" void kernel_launch(void* const* d_in, const int* in_sizes, int n_in,
                              void* d_out, int out_size)
{
    const float* X      = (const float*)d_in[0];   // [M, K] fp32
    const int*   W      = (const int*)d_in[1];     // [N, K] int32 (int8 values)
    const float* Wscale = (const float*)d_in[2];   // [N] fp32
    const float* Bias   = (const float*)d_in[3];   // [N] fp32
    float*       Out    = (float*)d_out;           // [M, N] fp32

    const size_t total_units = NXU8 + NWU8;
    const int prep_blocks = (int)((total_units + 511) / 512);
    prep_kernel<<<prep_blocks, 512>>>(X, W);

    static int smem_set = 0;
    if (!smem_set) {
        cudaFuncSetAttribute(gemm_f16_kernel,
                             cudaFuncAttributeMaxDynamicSharedMemorySize, SMEM_SZ);
        smem_set = 1;
    }
    gemm_f16_kernel<<<TILES_M * TILES_N, 128, SMEM_SZ>>>(Wscale, Bias, Out);
}